// round 8
// baseline (speedup 1.0000x reference)
#include <cuda_runtime.h>
#include <cstdint>

// CRF Viterbi decode: B=128, T=1024, K=128
// out[b,t,k] = one_hot(tags[b,t]) fp32
//
// 1 CTA/batch. Warp 0 runs the serial Viterbi recurrence with exact candidate
// pruning; warps 1-3 stage the logit stream through a double-buffered smem
// ring. Steps are processed in FUSED PAIRS: one REDUX+ballot collective round
// serves two time steps (step B's candidate set is derived from interval
// bounds LB1<=bv<=UB1 plus a state-independent logit-row reduction).

static constexpr int B_ = 128;
static constexpr int T_ = 1024;
static constexpr int K_ = 128;
static constexpr int CHUNK = 16;                      // rows per ring buffer (even)

// Shared memory layout (in 4-byte words)
static constexpr int TT_WORDS  = K_ * K_;             // 16384 row-major transitions
static constexpr int RMIN_OFF  = TT_WORDS;            // 16384
static constexpr int RMAX_OFF  = RMIN_OFF + K_;       // 16512
static constexpr int TAGS_OFF  = RMAX_OFF + K_;       // 16640
static constexpr int BP_OFF    = TAGS_OFF + T_;       // 17664 (u32/(t,lane): 4 packed u8 bp)
static constexpr int RING_OFF  = BP_OFF + T_ * 32;    // 50432 (2 x CHUNK x 128 floats)
static constexpr int SMEM_WORDS = RING_OFF + 2 * CHUNK * K_;  // 54528
static constexpr size_t SMEM_BYTES = (size_t)SMEM_WORDS * 4;  // 218112 B

// Safety slack for association-rounding drift of 3-term fp32 sums (|x| <= 8192
// => drift <= ~0.004). Only loosens the pruning bound; exactness preserved.
static constexpr float EPS_ASSOC = 0.05f;

// Monotone fp32 <-> ordered signed-int key (order-preserving bijection)
__device__ __forceinline__ int f2key(float x) {
    int i = __float_as_int(x);
    return i ^ ((i >> 31) & 0x7fffffff);
}
__device__ __forceinline__ float key2f(int k) {
    return __int_as_float(k ^ ((k >> 31) & 0x7fffffff));
}

// Extract lowest set bit position from 128-bit mask (A:H), branchless; clears it.
// Bit p: q = p>>5, cl = p&31, tag i = 4*cl + q.
__device__ __forceinline__ int ext128(unsigned long long& A, unsigned long long& H) {
    bool ua = (A != 0ull);
    int  pa = __ffsll((long long)A) - 1;
    int  ph = 63 + __ffsll((long long)H);
    int  p  = ua ? pa : ph;
    unsigned long long A2 = A & (A - 1ull);
    unsigned long long H2 = H & (H - 1ull);
    A = ua ? A2 : A;
    H = ua ? H : H2;
    return p;
}

// Exact composite argmax merge: max value, smallest index on ties.
__device__ __forceinline__ void cmerge(float va, int ia, float vb, int ib,
                                       float& vo, int& io) {
    bool g = (vb > va) || (vb == va && ib < ia);
    vo = g ? vb : va;
    io = g ? ib : ia;
}

__global__ void __launch_bounds__(128, 1)
viterbi_kernel(const float* __restrict__ logits,
               const int*   __restrict__ lens,
               const float* __restrict__ trans,
               float*       __restrict__ out)
{
    extern __shared__ float sm[];
    float*    Tt    = sm;
    float*    rminS = sm + RMIN_OFF;
    float*    rmaxS = sm + RMAX_OFF;
    int*      tagsS = (int*)(sm + TAGS_OFF);
    unsigned* bpS   = (unsigned*)(sm + BP_OFF);
    float4*   ring4 = (float4*)(sm + RING_OFF);       // [2][CHUNK][32] float4

    const int b    = blockIdx.x;
    const int tid  = threadIdx.x;
    const int lane = tid & 31;
    const int warp = tid >> 5;
    const unsigned F = 0xffffffffu;

    int L = lens[b];
    L = L < 1 ? 1 : (L > T_ ? T_ : L);
    const float*  lg  = logits + (size_t)b * T_ * K_;
    const float4* lg4 = (const float4*)lg;            // index: t*32 + c

    // ---- Prologue: transitions -> smem, row-major ----
    {
        const float4* t4g = (const float4*)trans;
        float4*       d4  = (float4*)Tt;
        for (int i = tid; i < (K_ * K_) / 4; i += 128) d4[i] = t4g[i];
    }
    __syncthreads();

    // ---- Per-row min/max (thread = row; rotated column order -> conflict-free) ----
    {
        const float4* rowp = (const float4*)(Tt + tid * K_);
        float mn = __int_as_float(0x7f800000);
        float mx = __int_as_float(0xff800000);
        #pragma unroll
        for (int c0 = 0; c0 < 32; ++c0) {
            int c = (c0 + tid) & 31;
            float4 v = rowp[c];
            mn = fminf(mn, fminf(fminf(v.x, v.y), fminf(v.z, v.w)));
            mx = fmaxf(mx, fmaxf(fmaxf(v.x, v.y), fmaxf(v.z, v.w)));
        }
        rminS[tid] = mn;
        rmaxS[tid] = mx;
    }

    // ---- Prefill ring buffer 0 with logit rows [1, 1+CHUNK) (producers) ----
    if (warp != 0) {
        int ptid = tid - 32;                          // 0..95
        for (int i = ptid; i < CHUNK * 32; i += 96) {
            int r = 1 + (i >> 5); r = r < T_ ? r : T_ - 1;
            ring4[i] = lg4[r * 32 + (i & 31)];
        }
    }
    __syncthreads();

    // Persistent warp-0 registers.
    float s[4], an[4], ax[4], rmn[4], rmx[4];
    if (warp == 0) {
        float4 rmn4 = ((const float4*)rminS)[lane];
        float4 rmx4 = ((const float4*)rmaxS)[lane];
        rmn[0]=rmn4.x; rmn[1]=rmn4.y; rmn[2]=rmn4.z; rmn[3]=rmn4.w;
        rmx[0]=rmx4.x; rmx[1]=rmx4.y; rmx[2]=rmx4.z; rmx[3]=rmx4.w;
        float4 v0 = lg4[lane];                        // t=0 logits = init state
        s[0]=v0.x; s[1]=v0.y; s[2]=v0.z; s[3]=v0.w;
        #pragma unroll
        for (int q = 0; q < 4; ++q) { an[q] = s[q] + rmn[q]; ax[q] = s[q] + rmx[q]; }
    }

    const float4* Trow4 = (const float4*)Tt;          // index: i*32 + lane

    // Process C-set masks (A:H) into (bv0..3, bi0..3) given state-shfl inputs.
    // All lanes take the same path (masks are warp-uniform).
    auto process_set = [&](unsigned long long A, unsigned long long H, int n,
                           float s0, float s1, float s2, float s3,
                           float& bv0, float& bv1, float& bv2, float& bv3,
                           int& bi0, int& bi1, int& bi2, int& bi3) {
        int p0 = ext128(A, H);
        int p1t = ext128(A, H);
        int p1 = (n > 1) ? p1t : p0;

        int c0l = p0 & 31, q0 = p0 >> 5, i0c = 4 * c0l + q0;
        int c1l = p1 & 31, q1 = p1 >> 5, i1c = 4 * c1l + q1;

        float w0 = q0 == 0 ? s0 : q0 == 1 ? s1 : q0 == 2 ? s2 : s3;
        float w1 = q1 == 0 ? s0 : q1 == 1 ? s1 : q1 == 2 ? s2 : s3;
        float sc0 = __shfl_sync(F, w0, c0l);
        float sc1 = __shfl_sync(F, w1, c1l);

        float4 tr0 = Trow4[i0c * 32 + lane];
        float4 tr1 = Trow4[i1c * 32 + lane];

        cmerge(sc0 + tr0.x, i0c, sc1 + tr1.x, i1c, bv0, bi0);
        cmerge(sc0 + tr0.y, i0c, sc1 + tr1.y, i1c, bv1, bi1);
        cmerge(sc0 + tr0.z, i0c, sc1 + tr1.z, i1c, bv2, bi2);
        cmerge(sc0 + tr0.w, i0c, sc1 + tr1.w, i1c, bv3, bi3);

        if (n > 2) {
            while (A | H) {
                int p = ext128(A, H);
                int clr = p & 31, qr = p >> 5, ir = 4 * clr + qr;
                float vr = qr == 0 ? s0 : qr == 1 ? s1 : qr == 2 ? s2 : s3;
                float scr = __shfl_sync(F, vr, clr);
                float4 trr = Trow4[ir * 32 + lane];
                cmerge(bv0, bi0, scr + trr.x, ir, bv0, bi0);
                cmerge(bv1, bi1, scr + trr.y, ir, bv1, bi1);
                cmerge(bv2, bi2, scr + trr.z, ir, bv2, bi2);
                cmerge(bv3, bi3, scr + trr.w, ir, bv3, bi3);
            }
        }
    };

    // ---- Chunked forward loop ----
    const int nchunks = (L + CHUNK - 2) / CHUNK;      // ceil((L-1)/CHUNK)
    for (int ci = 0; ci < nchunks; ++ci) {
        const int base = 1 + ci * CHUNK;

        if (warp != 0) {
            int ptid = tid - 32;
            float4* dst = ring4 + ((ci + 1) & 1) * (CHUNK * 32);
            int nb = base + CHUNK;
            #pragma unroll 2
            for (int i = ptid; i < CHUNK * 32; i += 96) {
                int r = nb + (i >> 5); r = r < T_ ? r : T_ - 1;
                dst[i] = lg4[r * 32 + (i & 31)];
            }
        } else {
            const float4* src = ring4 + (ci & 1) * (CHUNK * 32);
            int tend = base + CHUNK < L ? base + CHUNK : L;
            int tt = base;

            // ===== fused pairs (tt, tt+1) =====
            for (; tt + 1 < tend; tt += 2) {
                float4 clA = src[(tt - base) * 32 + lane];       // logit row tt
                float4 clB = src[(tt + 1 - base) * 32 + lane];   // logit row tt+1

                // off-chain: row-A combined terms for the C2 interval test
                float cn0 = clA.x + rmn[0], cn1 = clA.y + rmn[1];
                float cn2 = clA.z + rmn[2], cn3 = clA.w + rmn[3];
                float cx0 = clA.x + rmx[0], cx1 = clA.y + rmx[1];
                float cx2 = clA.z + rmx[2], cx3 = clA.w + rmx[3];
                float gl = fmaxf(fmaxf(cn0, cn1), fmaxf(cn2, cn3));

                // ---- collective round (once per pair) ----
                float am  = fmaxf(fmaxf(an[0], an[1]), fmaxf(an[2], an[3]));
                int  kLB = __reduce_max_sync(F, f2key(am));      // critical
                float xm  = fmaxf(fmaxf(ax[0], ax[1]), fmaxf(ax[2], ax[3]));
                int  kUB = __reduce_max_sync(F, f2key(xm));
                int  kG  = __reduce_max_sync(F, f2key(gl));

                // C1 ballots (exact int-key compare)
                unsigned a0 = __ballot_sync(F, f2key(ax[0]) >= kLB);
                unsigned a1 = __ballot_sync(F, f2key(ax[1]) >= kLB);
                unsigned a2 = __ballot_sync(F, f2key(ax[2]) >= kLB);
                unsigned a3 = __ballot_sync(F, f2key(ax[3]) >= kLB);

                // C2 ballots from interval bounds (state-independent operands)
                float LB1 = key2f(kLB);
                float UB1 = key2f(kUB);
                float th  = LB1 + key2f(kG) - EPS_ASSOC;
                unsigned b0 = __ballot_sync(F, (UB1 + cx0) >= th);
                unsigned b1 = __ballot_sync(F, (UB1 + cx1) >= th);
                unsigned b2 = __ballot_sync(F, (UB1 + cx2) >= th);
                unsigned b3 = __ballot_sync(F, (UB1 + cx3) >= th);

                unsigned long long A1 = (unsigned long long)a0 | ((unsigned long long)a1 << 32);
                unsigned long long H1 = (unsigned long long)a2 | ((unsigned long long)a3 << 32);
                unsigned long long A2 = (unsigned long long)b0 | ((unsigned long long)b1 << 32);
                unsigned long long H2 = (unsigned long long)b2 | ((unsigned long long)b3 << 32);
                int n1 = __popcll(A1) + __popcll(H1);
                int n2 = __popcll(A2) + __popcll(H2);

                // ---- step A: s_tt from s_{tt-1} over C1 ----
                float bv0, bv1, bv2, bv3; int bi0, bi1, bi2, bi3;
                process_set(A1, H1, n1, s[0], s[1], s[2], s[3],
                            bv0, bv1, bv2, bv3, bi0, bi1, bi2, bi3);
                s[0] = bv0 + clA.x;
                s[1] = bv1 + clA.y;
                s[2] = bv2 + clA.z;
                s[3] = bv3 + clA.w;
                bpS[tt * 32 + lane] = (unsigned)bi0 | ((unsigned)bi1 << 8) |
                                      ((unsigned)bi2 << 16) | ((unsigned)bi3 << 24);

                // ---- step B: s_{tt+1} from s_tt over C2 (no new collectives) ----
                float dv0, dv1, dv2, dv3; int di0, di1, di2, di3;
                process_set(A2, H2, n2, s[0], s[1], s[2], s[3],
                            dv0, dv1, dv2, dv3, di0, di1, di2, di3);
                s[0] = dv0 + clB.x;
                s[1] = dv1 + clB.y;
                s[2] = dv2 + clB.z;
                s[3] = dv3 + clB.w;
                bpS[(tt + 1) * 32 + lane] = (unsigned)di0 | ((unsigned)di1 << 8) |
                                            ((unsigned)di2 << 16) | ((unsigned)di3 << 24);

                // next-pair bound operands (latency shadow)
                an[0] = s[0] + rmn[0]; ax[0] = s[0] + rmx[0];
                an[1] = s[1] + rmn[1]; ax[1] = s[1] + rmx[1];
                an[2] = s[2] + rmn[2]; ax[2] = s[2] + rmx[2];
                an[3] = s[3] + rmn[3]; ax[3] = s[3] + rmx[3];
            }

            // ===== leftover single step (at most one, last chunk only) =====
            if (tt < tend) {
                float4 clt = src[(tt - base) * 32 + lane];

                float am  = fmaxf(fmaxf(an[0], an[1]), fmaxf(an[2], an[3]));
                int  kLB = __reduce_max_sync(F, f2key(am));
                unsigned a0 = __ballot_sync(F, f2key(ax[0]) >= kLB);
                unsigned a1 = __ballot_sync(F, f2key(ax[1]) >= kLB);
                unsigned a2 = __ballot_sync(F, f2key(ax[2]) >= kLB);
                unsigned a3 = __ballot_sync(F, f2key(ax[3]) >= kLB);
                unsigned long long A1 = (unsigned long long)a0 | ((unsigned long long)a1 << 32);
                unsigned long long H1 = (unsigned long long)a2 | ((unsigned long long)a3 << 32);
                int n1 = __popcll(A1) + __popcll(H1);

                float bv0, bv1, bv2, bv3; int bi0, bi1, bi2, bi3;
                process_set(A1, H1, n1, s[0], s[1], s[2], s[3],
                            bv0, bv1, bv2, bv3, bi0, bi1, bi2, bi3);
                s[0] = bv0 + clt.x;
                s[1] = bv1 + clt.y;
                s[2] = bv2 + clt.z;
                s[3] = bv3 + clt.w;
                bpS[tt * 32 + lane] = (unsigned)bi0 | ((unsigned)bi1 << 8) |
                                      ((unsigned)bi2 << 16) | ((unsigned)bi3 << 24);

                an[0] = s[0] + rmn[0]; ax[0] = s[0] + rmx[0];
                an[1] = s[1] + rmn[1]; ax[1] = s[1] + rmx[1];
                an[2] = s[2] + rmn[2]; ax[2] = s[2] + rmx[2];
                an[3] = s[3] + rmn[3]; ax[3] = s[3] + rmx[3];
            }
        }
        __syncthreads();   // chunk handoff
    }

    if (warp == 0) {
        // ---- last_tag = first argmax of final state ----
        float fm = fmaxf(fmaxf(s[0], s[1]), fmaxf(s[2], s[3]));
        int   mk = __reduce_max_sync(F, f2key(fm));
        float M  = key2f(mk);
        unsigned cand = 0x7fffffffu;
        #pragma unroll
        for (int q = 0; q < 4; ++q) {
            unsigned tg = (unsigned)(4 * lane + q);
            cand = (s[q] == M && tg < cand) ? tg : cand;
        }
        int last = (int)__reduce_min_sync(F, cand);

        for (int t = L - 1 + lane; t < T_; t += 32) tagsS[t] = last;

        // ---- backtrack: byte-addressed LDS chain ----
        if (lane == 0) {
            const unsigned char* bpB = (const unsigned char*)bpS;
            int cur = last;
            for (int t = L - 1; t >= 1; --t) {
                cur = bpB[t * 128 + cur];
                tagsS[t - 1] = cur;
            }
        }
    }
    __syncthreads();

    // ---- one-hot epilogue: 512 KB per CTA, coalesced STG.128 ----
    float4* out4 = (float4*)(out + (size_t)b * T_ * K_);
    for (int idx = tid; idx < T_ * (K_ / 4); idx += 128) {
        int t = idx >> 5;
        int c = (idx & 31) * 4;
        int tag = tagsS[t];
        float4 v;
        v.x = (tag == c    ) ? 1.f : 0.f;
        v.y = (tag == c + 1) ? 1.f : 0.f;
        v.z = (tag == c + 2) ? 1.f : 0.f;
        v.w = (tag == c + 3) ? 1.f : 0.f;
        out4[idx] = v;
    }
}

extern "C" void kernel_launch(void* const* d_in, const int* in_sizes, int n_in,
                              void* d_out, int out_size)
{
    const float* logits = (const float*)d_in[0];
    const int*   lens   = (const int*)d_in[1];
    const float* trans  = (const float*)d_in[2];
    float*       out    = (float*)d_out;

    cudaFuncSetAttribute(viterbi_kernel,
                         cudaFuncAttributeMaxDynamicSharedMemorySize,
                         (int)SMEM_BYTES);
    viterbi_kernel<<<B_, 128, SMEM_BYTES>>>(logits, lens, trans, out);
}

// round 10
// speedup vs baseline: 1.3278x; 1.3278x over previous
#include <cuda_runtime.h>
#include <cstdint>

// CRF Viterbi decode: B=128, T=1024, K=128
// out[b,t,k] = one_hot(tags[b,t]) fp32
//
// 1 CTA/batch. Warp 0 runs the serial Viterbi recurrence with exact candidate
// pruning; warps 1-3 stage the logit stream through a double-buffered smem
// ring. The per-step REDUX carries a packed (truncated-key | 127-index) so the
// argmax row i* (always a valid candidate) is known immediately after the
// REDUX -- its SHFL+LDS launch without waiting for any ballot. A single
// 32-bit ballot over per-lane candidate nibbles finds extra candidates.

static constexpr int B_ = 128;
static constexpr int T_ = 1024;
static constexpr int K_ = 128;
static constexpr int CHUNK = 16;                      // rows per ring buffer

// Shared memory layout (in 4-byte words)
static constexpr int TT_WORDS  = K_ * K_;             // 16384 row-major transitions
static constexpr int RMIN_OFF  = TT_WORDS;            // 16384
static constexpr int RMAX_OFF  = RMIN_OFF + K_;       // 16512
static constexpr int TAGS_OFF  = RMAX_OFF + K_;       // 16640
static constexpr int BP_OFF    = TAGS_OFF + T_;       // 17664 (u32/(t,lane): 4 packed u8 bp)
static constexpr int RING_OFF  = BP_OFF + T_ * 32;    // 50432 (2 x CHUNK x 128 floats)
static constexpr int SMEM_WORDS = RING_OFF + 2 * CHUNK * K_;  // 54528
static constexpr size_t SMEM_BYTES = (size_t)SMEM_WORDS * 4;  // 218112 B

// Monotone fp32 <-> ordered signed-int key (order-preserving bijection)
__device__ __forceinline__ int f2key(float x) {
    int i = __float_as_int(x);
    return i ^ ((i >> 31) & 0x7fffffff);
}

// Exact composite argmax merge: max value, smallest index on ties.
__device__ __forceinline__ void cmerge(float va, int ia, float vb, int ib,
                                       float& vo, int& io) {
    bool g = (vb > va) || (vb == va && ib < ia);
    vo = g ? vb : va;
    io = g ? ib : ia;
}

__global__ void __launch_bounds__(128, 1)
viterbi_kernel(const float* __restrict__ logits,
               const int*   __restrict__ lens,
               const float* __restrict__ trans,
               float*       __restrict__ out)
{
    extern __shared__ float sm[];
    float*    Tt    = sm;
    float*    rminS = sm + RMIN_OFF;
    float*    rmaxS = sm + RMAX_OFF;
    int*      tagsS = (int*)(sm + TAGS_OFF);
    unsigned* bpS   = (unsigned*)(sm + BP_OFF);
    float4*   ring4 = (float4*)(sm + RING_OFF);       // [2][CHUNK][32] float4

    const int b    = blockIdx.x;
    const int tid  = threadIdx.x;
    const int lane = tid & 31;
    const int warp = tid >> 5;
    const int lane4 = lane << 2;                      // 4*lane
    const unsigned F = 0xffffffffu;

    int L = lens[b];
    L = L < 1 ? 1 : (L > T_ ? T_ : L);
    const float*  lg  = logits + (size_t)b * T_ * K_;
    const float4* lg4 = (const float4*)lg;            // index: t*32 + c

    // ---- Prologue: transitions -> smem, row-major ----
    {
        const float4* t4g = (const float4*)trans;
        float4*       d4  = (float4*)Tt;
        for (int i = tid; i < (K_ * K_) / 4; i += 128) d4[i] = t4g[i];
    }
    __syncthreads();

    // ---- Per-row min/max (thread = row; rotated column order -> conflict-free) ----
    {
        const float4* rowp = (const float4*)(Tt + tid * K_);
        float mn = __int_as_float(0x7f800000);
        float mx = __int_as_float(0xff800000);
        #pragma unroll
        for (int c0 = 0; c0 < 32; ++c0) {
            int c = (c0 + tid) & 31;
            float4 v = rowp[c];
            mn = fminf(mn, fminf(fminf(v.x, v.y), fminf(v.z, v.w)));
            mx = fmaxf(mx, fmaxf(fmaxf(v.x, v.y), fmaxf(v.z, v.w)));
        }
        rminS[tid] = mn;
        rmaxS[tid] = mx;
    }

    // ---- Prefill ring buffer 0 with logit rows [1, 1+CHUNK) (producers) ----
    if (warp != 0) {
        int ptid = tid - 32;                          // 0..95
        for (int i = ptid; i < CHUNK * 32; i += 96) {
            int r = 1 + (i >> 5); r = r < T_ ? r : T_ - 1;
            ring4[i] = lg4[r * 32 + (i & 31)];
        }
    }
    __syncthreads();

    // Persistent warp-0 registers.
    // kp   = local max over 4 slots of ((f2key(s+rmn) & ~127) | (127 - i))
    // ux[q]= f2key(s[q] + rmx[q])
    float s[4], rmn[4], rmx[4];
    int   kp, ux0, ux1, ux2, ux3;
    if (warp == 0) {
        float4 rmn4 = ((const float4*)rminS)[lane];
        float4 rmx4 = ((const float4*)rmaxS)[lane];
        rmn[0]=rmn4.x; rmn[1]=rmn4.y; rmn[2]=rmn4.z; rmn[3]=rmn4.w;
        rmx[0]=rmx4.x; rmx[1]=rmx4.y; rmx[2]=rmx4.z; rmx[3]=rmx4.w;
        float4 v0 = lg4[lane];                        // t=0 logits = init state
        s[0]=v0.x; s[1]=v0.y; s[2]=v0.z; s[3]=v0.w;
        int kq0 = (f2key(s[0] + rmn[0]) & ~127) | (127 - (lane4 + 0));
        int kq1 = (f2key(s[1] + rmn[1]) & ~127) | (127 - (lane4 + 1));
        int kq2 = (f2key(s[2] + rmn[2]) & ~127) | (127 - (lane4 + 2));
        int kq3 = (f2key(s[3] + rmn[3]) & ~127) | (127 - (lane4 + 3));
        kp = max(max(kq0, kq1), max(kq2, kq3));
        ux0 = f2key(s[0] + rmx[0]);
        ux1 = f2key(s[1] + rmx[1]);
        ux2 = f2key(s[2] + rmx[2]);
        ux3 = f2key(s[3] + rmx[3]);
    }

    const float4* Trow4 = (const float4*)Tt;          // index: i*32 + lane

    // ---- Chunked forward loop: producers stage chunk ci+1 while warp 0 eats ci ----
    const int nchunks = (L + CHUNK - 2) / CHUNK;      // ceil((L-1)/CHUNK)
    for (int ci = 0; ci < nchunks; ++ci) {
        const int base = 1 + ci * CHUNK;

        if (warp != 0) {
            int ptid = tid - 32;
            float4* dst = ring4 + ((ci + 1) & 1) * (CHUNK * 32);
            int nb = base + CHUNK;
            #pragma unroll 2
            for (int i = ptid; i < CHUNK * 32; i += 96) {
                int r = nb + (i >> 5); r = r < T_ ? r : T_ - 1;
                dst[i] = lg4[r * 32 + (i & 31)];
            }
        } else {
            const float4* src = ring4 + (ci & 1) * (CHUNK * 32);
            int tend = base + CHUNK < L ? base + CHUNK : L;
            for (int t = base; t < tend; ++t) {
                float4 clt = src[(t - base) * 32 + lane];   // logit row t (smem)

                // ---- single packed REDUX: LB key + argmax index in one op ----
                int r = __reduce_max_sync(F, kp);
                int kLB   = r & ~127;                  // truncated key: valid LB
                int istar = 127 - (r & 127);           // argmax(s+rmn): always a candidate
                int clS = istar >> 2, qS = istar & 3;  // warp-uniform

                // PATH A: candidate i* (no ballot needed)
                float wA  = qS == 0 ? s[0] : qS == 1 ? s[1] : qS == 2 ? s[2] : s[3];
                float scA = __shfl_sync(F, wA, clS);
                float4 trA = Trow4[istar * 32 + lane];

                // PATH B: extra candidates via per-lane nibble + one ballot
                unsigned nib = (ux0 >= kLB ? 1u : 0u) | (ux1 >= kLB ? 2u : 0u)
                             | (ux2 >= kLB ? 4u : 0u) | (ux3 >= kLB ? 8u : 0u);
                nib &= ~(((lane == clS) ? 1u : 0u) << qS);   // drop i* (owner lane)

                unsigned qloc = nib ? (unsigned)(__ffs(nib) - 1) : 0u;
                float sloc = qloc == 0 ? s[0] : qloc == 1 ? s[1] : qloc == 2 ? s[2] : s[3];
                int   iloc = lane4 + (int)qloc;
                unsigned multi = nib & (nib - 1);

                unsigned em = __ballot_sync(F, nib != 0u);
                unsigned mm = __ballot_sync(F, multi != 0u);

                int clB = em ? (__ffs(em) - 1) : clS;  // fallback: real row, safe
                float scB = __shfl_sync(F, sloc, clB);
                int   iB  = __shfl_sync(F, iloc, clB);
                float4 trB = Trow4[iB * 32 + lane];

                float bv0, bv1, bv2, bv3;  int bi0, bi1, bi2, bi3;
                cmerge(scA + trA.x, istar, scB + trB.x, iB, bv0, bi0);
                cmerge(scA + trA.y, istar, scB + trB.y, iB, bv1, bi1);
                cmerge(scA + trA.z, istar, scB + trB.z, iB, bv2, bi2);
                cmerge(scA + trA.w, istar, scB + trB.w, iB, bv3, bi3);

                // ---- rare: >1 extra lane, or a lane with multiple extras ----
                unsigned em2 = em & (em - 1);
                if (em2 | mm) {
                    unsigned rem = em2 | mm;           // re-scan lanes (idempotent merges)
                    while (rem) {
                        int cl = __ffs(rem) - 1; rem &= rem - 1;
                        unsigned nb = __shfl_sync(F, nib, cl);
                        while (nb) {
                            int q = __ffs(nb) - 1; nb &= nb - 1;   // q warp-uniform
                            int i = 4 * cl + q;
                            float sv = q == 0 ? s[0] : q == 1 ? s[1] : q == 2 ? s[2] : s[3];
                            float sc = __shfl_sync(F, sv, cl);
                            float4 tr = Trow4[i * 32 + lane];
                            cmerge(bv0, bi0, sc + tr.x, i, bv0, bi0);
                            cmerge(bv1, bi1, sc + tr.y, i, bv1, bi1);
                            cmerge(bv2, bi2, sc + tr.z, i, bv2, bi2);
                            cmerge(bv3, bi3, sc + tr.w, i, bv3, bi3);
                        }
                    }
                }

                // ---- state update + next-step operands (latency shadow) ----
                s[0] = bv0 + clt.x;
                s[1] = bv1 + clt.y;
                s[2] = bv2 + clt.z;
                s[3] = bv3 + clt.w;
                int kq0 = (f2key(s[0] + rmn[0]) & ~127) | (127 - (lane4 + 0));
                int kq1 = (f2key(s[1] + rmn[1]) & ~127) | (127 - (lane4 + 1));
                int kq2 = (f2key(s[2] + rmn[2]) & ~127) | (127 - (lane4 + 2));
                int kq3 = (f2key(s[3] + rmn[3]) & ~127) | (127 - (lane4 + 3));
                kp = max(max(kq0, kq1), max(kq2, kq3));
                ux0 = f2key(s[0] + rmx[0]);
                ux1 = f2key(s[1] + rmx[1]);
                ux2 = f2key(s[2] + rmx[2]);
                ux3 = f2key(s[3] + rmx[3]);

                bpS[t * 32 + lane] = (unsigned)bi0 | ((unsigned)bi1 << 8) |
                                     ((unsigned)bi2 << 16) | ((unsigned)bi3 << 24);
            }
        }
        __syncthreads();   // chunk handoff
    }

    if (warp == 0) {
        // ---- last_tag = first argmax of final state ----
        float fm = fmaxf(fmaxf(s[0], s[1]), fmaxf(s[2], s[3]));
        int   mk = __reduce_max_sync(F, f2key(fm));
        unsigned cand = 0x7fffffffu;
        #pragma unroll
        for (int q = 0; q < 4; ++q) {
            unsigned tg = (unsigned)(lane4 + q);
            cand = (f2key(s[q]) == mk && tg < cand) ? tg : cand;
        }
        int last = (int)__reduce_min_sync(F, cand);

        for (int t = L - 1 + lane; t < T_; t += 32) tagsS[t] = last;

        // ---- backtrack: byte-addressed LDS chain ----
        if (lane == 0) {
            const unsigned char* bpB = (const unsigned char*)bpS;
            int cur = last;
            for (int t = L - 1; t >= 1; --t) {
                cur = bpB[t * 128 + cur];
                tagsS[t - 1] = cur;
            }
        }
    }
    __syncthreads();

    // ---- one-hot epilogue: 512 KB per CTA, coalesced STG.128 ----
    float4* out4 = (float4*)(out + (size_t)b * T_ * K_);
    for (int idx = tid; idx < T_ * (K_ / 4); idx += 128) {
        int t = idx >> 5;
        int c = (idx & 31) * 4;
        int tag = tagsS[t];
        float4 v;
        v.x = (tag == c    ) ? 1.f : 0.f;
        v.y = (tag == c + 1) ? 1.f : 0.f;
        v.z = (tag == c + 2) ? 1.f : 0.f;
        v.w = (tag == c + 3) ? 1.f : 0.f;
        out4[idx] = v;
    }
}

extern "C" void kernel_launch(void* const* d_in, const int* in_sizes, int n_in,
                              void* d_out, int out_size)
{
    const float* logits = (const float*)d_in[0];
    const int*   lens   = (const int*)d_in[1];
    const float* trans  = (const float*)d_in[2];
    float*       out    = (float*)d_out;

    cudaFuncSetAttribute(viterbi_kernel,
                         cudaFuncAttributeMaxDynamicSharedMemorySize,
                         (int)SMEM_BYTES);
    viterbi_kernel<<<B_, 128, SMEM_BYTES>>>(logits, lens, trans, out);
}

// round 11
// speedup vs baseline: 1.4153x; 1.0659x over previous
#include <cuda_runtime.h>
#include <cstdint>

// CRF Viterbi decode: B=128, T=1024, K=128
// out[b,t,k] = one_hot(tags[b,t]) fp32
//
// 1 CTA/batch. Warp 0 runs the serial Viterbi recurrence with exact candidate
// pruning; warps 1-3 stage the logit stream through a double-buffered smem
// ring. Pruning bounds use bias-shifted positive floats so the warp REDUX runs
// on raw fp32 bits (no int-key transform in the loop); ballot compares are
// plain float FSETPs. LDS addresses derive from ballot masks via pure ALU
// (no SHFL on any address path).

static constexpr int B_ = 128;
static constexpr int T_ = 1024;
static constexpr int K_ = 128;
static constexpr int CHUNK = 16;                      // rows per ring buffer

static constexpr float BIGF  = 16384.0f;              // positivity bias
static constexpr float SLACK = 0.02f;                 // covers double-rounding at 2^14

// Shared memory layout (in 4-byte words)
static constexpr int TT_WORDS  = K_ * K_;             // 16384 row-major transitions
static constexpr int RMIN_OFF  = TT_WORDS;            // 16384
static constexpr int RMAX_OFF  = RMIN_OFF + K_;       // 16512
static constexpr int TAGS_OFF  = RMAX_OFF + K_;       // 16640
static constexpr int BP_OFF    = TAGS_OFF + T_;       // 17664 (u32/(t,lane): 4 packed u8 bp)
static constexpr int RING_OFF  = BP_OFF + T_ * 32;    // 50432 (2 x CHUNK x 128 floats)
static constexpr int SMEM_WORDS = RING_OFF + 2 * CHUNK * K_;  // 54528
static constexpr size_t SMEM_BYTES = (size_t)SMEM_WORDS * 4;  // 218112 B

// Monotone fp32 <-> ordered signed-int key (used only outside the hot loop)
__device__ __forceinline__ int f2key(float x) {
    int i = __float_as_int(x);
    return i ^ ((i >> 31) & 0x7fffffff);
}

// Extract lowest set bit position from 128-bit mask (A:H), branchless; clears it.
// Bit p: q = p>>5, cl = p&31, tag i = 4*cl + q.
__device__ __forceinline__ int ext128(unsigned long long& A, unsigned long long& H) {
    bool ua = (A != 0ull);
    int  pa = __ffsll((long long)A) - 1;
    int  ph = 63 + __ffsll((long long)H);
    int  p  = ua ? pa : ph;
    unsigned long long A2 = A & (A - 1ull);
    unsigned long long H2 = H & (H - 1ull);
    A = ua ? A2 : A;
    H = ua ? H : H2;
    return p;
}

// Exact composite argmax merge: max value, smallest index on ties.
__device__ __forceinline__ void cmerge(float va, int ia, float vb, int ib,
                                       float& vo, int& io) {
    bool g = (vb > va) || (vb == va && ib < ia);
    vo = g ? vb : va;
    io = g ? ib : ia;
}

__global__ void __launch_bounds__(128, 1)
viterbi_kernel(const float* __restrict__ logits,
               const int*   __restrict__ lens,
               const float* __restrict__ trans,
               float*       __restrict__ out)
{
    extern __shared__ float sm[];
    float*    Tt    = sm;
    float*    rminS = sm + RMIN_OFF;
    float*    rmaxS = sm + RMAX_OFF;
    int*      tagsS = (int*)(sm + TAGS_OFF);
    unsigned* bpS   = (unsigned*)(sm + BP_OFF);
    float4*   ring4 = (float4*)(sm + RING_OFF);       // [2][CHUNK][32] float4

    const int b    = blockIdx.x;
    const int tid  = threadIdx.x;
    const int lane = tid & 31;
    const int warp = tid >> 5;
    const unsigned F = 0xffffffffu;

    int L = lens[b];
    L = L < 1 ? 1 : (L > T_ ? T_ : L);
    const float*  lg  = logits + (size_t)b * T_ * K_;
    const float4* lg4 = (const float4*)lg;            // index: t*32 + c

    // ---- Prologue: transitions -> smem, row-major ----
    {
        const float4* t4g = (const float4*)trans;
        float4*       d4  = (float4*)Tt;
        for (int i = tid; i < (K_ * K_) / 4; i += 128) d4[i] = t4g[i];
    }
    __syncthreads();

    // ---- Per-row min/max (thread = row; rotated column order -> conflict-free) ----
    {
        const float4* rowp = (const float4*)(Tt + tid * K_);
        float mn = __int_as_float(0x7f800000);
        float mx = __int_as_float(0xff800000);
        #pragma unroll
        for (int c0 = 0; c0 < 32; ++c0) {
            int c = (c0 + tid) & 31;
            float4 v = rowp[c];
            mn = fminf(mn, fminf(fminf(v.x, v.y), fminf(v.z, v.w)));
            mx = fmaxf(mx, fmaxf(fmaxf(v.x, v.y), fmaxf(v.z, v.w)));
        }
        rminS[tid] = mn;
        rmaxS[tid] = mx;
    }

    // ---- Prefill ring buffer 0 with logit rows [1, 1+CHUNK) (producers) ----
    if (warp != 0) {
        int ptid = tid - 32;                          // 0..95
        for (int i = ptid; i < CHUNK * 32; i += 96) {
            int r = 1 + (i >> 5); r = r < T_ ? r : T_ - 1;
            ring4[i] = lg4[r * 32 + (i & 31)];
        }
    }
    __syncthreads();

    // Persistent warp-0 registers.
    // rmnb = rmn + BIGF ; rmxb = (rmx + SLACK) + BIGF.
    // anb[q] = s[q] + rmnb[q] (positive => raw bits monotone for int REDUX).
    // axb[q] = s[q] + rmxb[q] (ballot operand; slack makes superset rigorous).
    float s[4], rmnb[4], rmxb[4], anb[4], axb[4];
    if (warp == 0) {
        float4 rmn4 = ((const float4*)rminS)[lane];
        float4 rmx4 = ((const float4*)rmaxS)[lane];
        rmnb[0] = rmn4.x + BIGF; rmnb[1] = rmn4.y + BIGF;
        rmnb[2] = rmn4.z + BIGF; rmnb[3] = rmn4.w + BIGF;
        rmxb[0] = (rmx4.x + SLACK) + BIGF; rmxb[1] = (rmx4.y + SLACK) + BIGF;
        rmxb[2] = (rmx4.z + SLACK) + BIGF; rmxb[3] = (rmx4.w + SLACK) + BIGF;
        float4 v0 = lg4[lane];                        // t=0 logits = init state
        s[0]=v0.x; s[1]=v0.y; s[2]=v0.z; s[3]=v0.w;
        #pragma unroll
        for (int q = 0; q < 4; ++q) { anb[q] = s[q] + rmnb[q]; axb[q] = s[q] + rmxb[q]; }
    }

    const float4* Trow4 = (const float4*)Tt;          // index: i*32 + lane

    // ---- Chunked forward loop: producers stage chunk ci+1 while warp 0 eats ci ----
    const int nchunks = (L + CHUNK - 2) / CHUNK;      // ceil((L-1)/CHUNK)
    for (int ci = 0; ci < nchunks; ++ci) {
        const int base = 1 + ci * CHUNK;

        if (warp != 0) {
            int ptid = tid - 32;
            float4* dst = ring4 + ((ci + 1) & 1) * (CHUNK * 32);
            int nb = base + CHUNK;
            #pragma unroll 2
            for (int i = ptid; i < CHUNK * 32; i += 96) {
                int r = nb + (i >> 5); r = r < T_ ? r : T_ - 1;
                dst[i] = lg4[r * 32 + (i & 31)];
            }
        } else {
            const float4* src = ring4 + (ci & 1) * (CHUNK * 32);
            int tend = base + CHUNK < L ? base + CHUNK : L;
            #pragma unroll 2
            for (int t = base; t < tend; ++t) {
                float4 clt = src[(t - base) * 32 + lane];   // logit row t (smem)

                // ---- LB: REDUX.MAX on raw bits of positive floats ----
                float am  = fmaxf(fmaxf(anb[0], anb[1]), fmaxf(anb[2], anb[3]));
                int   rI  = __reduce_max_sync(F, __float_as_int(am));
                float LBfs = __int_as_float(rI);

                // candidate ballots: plain float compares (slack in rmxb)
                unsigned m0 = __ballot_sync(F, axb[0] >= LBfs);
                unsigned m1 = __ballot_sync(F, axb[1] >= LBfs);
                unsigned m2 = __ballot_sync(F, axb[2] >= LBfs);
                unsigned m3 = __ballot_sync(F, axb[3] >= LBfs);

                unsigned long long A = (unsigned long long)m0 | ((unsigned long long)m1 << 32);
                unsigned long long H = (unsigned long long)m2 | ((unsigned long long)m3 << 32);

                // ---- 2-wide branchless candidate handling ----
                int p0 = ext128(A, H);
                bool more1 = (A | H) != 0ull;
                int p1t = ext128(A, H);
                int p1 = more1 ? p1t : p0;
                bool more2 = (A | H) != 0ull;

                int c0l = p0 & 31, q0 = p0 >> 5, i0c = 4 * c0l + q0;
                int c1l = p1 & 31, q1 = p1 >> 5, i1c = 4 * c1l + q1;

                float w0 = q0 == 0 ? s[0] : q0 == 1 ? s[1] : q0 == 2 ? s[2] : s[3];
                float w1 = q1 == 0 ? s[0] : q1 == 1 ? s[1] : q1 == 2 ? s[2] : s[3];
                float sc0 = __shfl_sync(F, w0, c0l);
                float sc1 = __shfl_sync(F, w1, c1l);

                float4 tr0 = Trow4[i0c * 32 + lane];   // both LDS.128 in flight together
                float4 tr1 = Trow4[i1c * 32 + lane];

                float bv0, bv1, bv2, bv3;  int bi0, bi1, bi2, bi3;
                cmerge(sc0 + tr0.x, i0c, sc1 + tr1.x, i1c, bv0, bi0);
                cmerge(sc0 + tr0.y, i0c, sc1 + tr1.y, i1c, bv1, bi1);
                cmerge(sc0 + tr0.z, i0c, sc1 + tr1.z, i1c, bv2, bi2);
                cmerge(sc0 + tr0.w, i0c, sc1 + tr1.w, i1c, bv3, bi3);

                // ---- rare overflow: remaining candidates serially ----
                if (more2) {
                    while (A | H) {
                        int p = ext128(A, H);
                        int clr = p & 31, qr = p >> 5, ir = 4 * clr + qr;
                        float vr = qr == 0 ? s[0] : qr == 1 ? s[1] : qr == 2 ? s[2] : s[3];
                        float scr = __shfl_sync(F, vr, clr);
                        float4 trr = Trow4[ir * 32 + lane];
                        cmerge(bv0, bi0, scr + trr.x, ir, bv0, bi0);
                        cmerge(bv1, bi1, scr + trr.y, ir, bv1, bi1);
                        cmerge(bv2, bi2, scr + trr.z, ir, bv2, bi2);
                        cmerge(bv3, bi3, scr + trr.w, ir, bv3, bi3);
                    }
                }

                // ---- state update + next-step bound operands (latency shadow) ----
                s[0] = bv0 + clt.x;
                s[1] = bv1 + clt.y;
                s[2] = bv2 + clt.z;
                s[3] = bv3 + clt.w;
                anb[0] = s[0] + rmnb[0]; axb[0] = s[0] + rmxb[0];
                anb[1] = s[1] + rmnb[1]; axb[1] = s[1] + rmxb[1];
                anb[2] = s[2] + rmnb[2]; axb[2] = s[2] + rmxb[2];
                anb[3] = s[3] + rmnb[3]; axb[3] = s[3] + rmxb[3];

                bpS[t * 32 + lane] = (unsigned)bi0 | ((unsigned)bi1 << 8) |
                                     ((unsigned)bi2 << 16) | ((unsigned)bi3 << 24);
            }
        }
        __syncthreads();   // chunk handoff
    }

    if (warp == 0) {
        // ---- last_tag = first argmax of final state (exact keys, off hot path) ----
        float fm = fmaxf(fmaxf(s[0], s[1]), fmaxf(s[2], s[3]));
        int   mk = __reduce_max_sync(F, f2key(fm));
        unsigned cand = 0x7fffffffu;
        #pragma unroll
        for (int q = 0; q < 4; ++q) {
            unsigned tg = (unsigned)(4 * lane + q);
            cand = (f2key(s[q]) == mk && tg < cand) ? tg : cand;
        }
        int last = (int)__reduce_min_sync(F, cand);

        for (int t = L - 1 + lane; t < T_; t += 32) tagsS[t] = last;

        // ---- backtrack: byte-addressed LDS chain ----
        if (lane == 0) {
            const unsigned char* bpB = (const unsigned char*)bpS;
            int cur = last;
            for (int t = L - 1; t >= 1; --t) {
                cur = bpB[t * 128 + cur];
                tagsS[t - 1] = cur;
            }
        }
    }
    __syncthreads();

    // ---- one-hot epilogue: 512 KB per CTA, coalesced STG.128 ----
    float4* out4 = (float4*)(out + (size_t)b * T_ * K_);
    for (int idx = tid; idx < T_ * (K_ / 4); idx += 128) {
        int t = idx >> 5;
        int c = (idx & 31) * 4;
        int tag = tagsS[t];
        float4 v;
        v.x = (tag == c    ) ? 1.f : 0.f;
        v.y = (tag == c + 1) ? 1.f : 0.f;
        v.z = (tag == c + 2) ? 1.f : 0.f;
        v.w = (tag == c + 3) ? 1.f : 0.f;
        out4[idx] = v;
    }
}

extern "C" void kernel_launch(void* const* d_in, const int* in_sizes, int n_in,
                              void* d_out, int out_size)
{
    const float* logits = (const float*)d_in[0];
    const int*   lens   = (const int*)d_in[1];
    const float* trans  = (const float*)d_in[2];
    float*       out    = (float*)d_out;

    cudaFuncSetAttribute(viterbi_kernel,
                         cudaFuncAttributeMaxDynamicSharedMemorySize,
                         (int)SMEM_BYTES);
    viterbi_kernel<<<B_, 128, SMEM_BYTES>>>(logits, lens, trans, out);
}

// round 12
// speedup vs baseline: 1.4935x; 1.0553x over previous
#include <cuda_runtime.h>
#include <cstdint>

// CRF Viterbi decode: B=128, T=1024, K=128
// out[b,t,k] = one_hot(tags[b,t]) fp32
//
// 1 CTA/batch. Warp 0 runs the serial Viterbi recurrence with exact candidate
// pruning; warps 1-3 stage the logit stream through a double-buffered smem
// ring. Pruning bounds are bias-shifted positive floats (raw-bit REDUX, no
// key transform). Candidate decode uses slot-encoded 32-bit ballots:
// em/lo/hi/mm -> pure-ALU addresses (no 64-bit ffs, no SHFL on address path).

static constexpr int B_ = 128;
static constexpr int T_ = 1024;
static constexpr int K_ = 128;
static constexpr int CHUNK = 16;                      // rows per ring buffer

static constexpr float BIGF  = 16384.0f;              // positivity bias
static constexpr float SLACK = 0.02f;                 // covers double-rounding at 2^14

// Shared memory layout (in 4-byte words)
static constexpr int TT_WORDS  = K_ * K_;             // 16384 row-major transitions
static constexpr int RMIN_OFF  = TT_WORDS;            // 16384
static constexpr int RMAX_OFF  = RMIN_OFF + K_;       // 16512
static constexpr int TAGS_OFF  = RMAX_OFF + K_;       // 16640
static constexpr int BP_OFF    = TAGS_OFF + T_;       // 17664 (u32/(t,lane): 4 packed u8 bp)
static constexpr int RING_OFF  = BP_OFF + T_ * 32;    // 50432 (2 x CHUNK x 128 floats)
static constexpr int SMEM_WORDS = RING_OFF + 2 * CHUNK * K_;  // 54528
static constexpr size_t SMEM_BYTES = (size_t)SMEM_WORDS * 4;  // 218112 B

// Monotone fp32 <-> ordered signed-int key (outside the hot loop only)
__device__ __forceinline__ int f2key(float x) {
    int i = __float_as_int(x);
    return i ^ ((i >> 31) & 0x7fffffff);
}

// Exact composite argmax merge: max value, smallest index on ties.
__device__ __forceinline__ void cmerge(float va, int ia, float vb, int ib,
                                       float& vo, int& io) {
    bool g = (vb > va) || (vb == va && ib < ia);
    vo = g ? vb : va;
    io = g ? ib : ia;
}

__global__ void __launch_bounds__(128, 1)
viterbi_kernel(const float* __restrict__ logits,
               const int*   __restrict__ lens,
               const float* __restrict__ trans,
               float*       __restrict__ out)
{
    extern __shared__ float sm[];
    float*    Tt    = sm;
    float*    rminS = sm + RMIN_OFF;
    float*    rmaxS = sm + RMAX_OFF;
    int*      tagsS = (int*)(sm + TAGS_OFF);
    unsigned* bpS   = (unsigned*)(sm + BP_OFF);
    float4*   ring4 = (float4*)(sm + RING_OFF);       // [2][CHUNK][32] float4

    const int b    = blockIdx.x;
    const int tid  = threadIdx.x;
    const int lane = tid & 31;
    const int warp = tid >> 5;
    const unsigned F = 0xffffffffu;

    int L = lens[b];
    L = L < 1 ? 1 : (L > T_ ? T_ : L);
    const float*  lg  = logits + (size_t)b * T_ * K_;
    const float4* lg4 = (const float4*)lg;            // index: t*32 + c

    // ---- Prologue: transitions -> smem, row-major ----
    {
        const float4* t4g = (const float4*)trans;
        float4*       d4  = (float4*)Tt;
        for (int i = tid; i < (K_ * K_) / 4; i += 128) d4[i] = t4g[i];
    }
    __syncthreads();

    // ---- Per-row min/max (thread = row; rotated column order -> conflict-free) ----
    {
        const float4* rowp = (const float4*)(Tt + tid * K_);
        float mn = __int_as_float(0x7f800000);
        float mx = __int_as_float(0xff800000);
        #pragma unroll
        for (int c0 = 0; c0 < 32; ++c0) {
            int c = (c0 + tid) & 31;
            float4 v = rowp[c];
            mn = fminf(mn, fminf(fminf(v.x, v.y), fminf(v.z, v.w)));
            mx = fmaxf(mx, fmaxf(fmaxf(v.x, v.y), fmaxf(v.z, v.w)));
        }
        rminS[tid] = mn;
        rmaxS[tid] = mx;
    }

    // ---- Prefill ring buffer 0 with logit rows [1, 1+CHUNK) (producers) ----
    if (warp != 0) {
        int ptid = tid - 32;                          // 0..95
        for (int i = ptid; i < CHUNK * 32; i += 96) {
            int r = 1 + (i >> 5); r = r < T_ ? r : T_ - 1;
            ring4[i] = lg4[r * 32 + (i & 31)];
        }
    }
    __syncthreads();

    // Persistent warp-0 registers.
    // rmnb = rmn + BIGF ; rmxb = (rmx + SLACK) + BIGF.
    // anb[q] = s[q] + rmnb[q] (positive => raw bits monotone for int REDUX).
    // axb[q] = s[q] + rmxb[q] (ballot operand; slack makes superset rigorous).
    float s[4], rmnb[4], rmxb[4], anb[4], axb[4];
    if (warp == 0) {
        float4 rmn4 = ((const float4*)rminS)[lane];
        float4 rmx4 = ((const float4*)rmaxS)[lane];
        rmnb[0] = rmn4.x + BIGF; rmnb[1] = rmn4.y + BIGF;
        rmnb[2] = rmn4.z + BIGF; rmnb[3] = rmn4.w + BIGF;
        rmxb[0] = (rmx4.x + SLACK) + BIGF; rmxb[1] = (rmx4.y + SLACK) + BIGF;
        rmxb[2] = (rmx4.z + SLACK) + BIGF; rmxb[3] = (rmx4.w + SLACK) + BIGF;
        float4 v0 = lg4[lane];                        // t=0 logits = init state
        s[0]=v0.x; s[1]=v0.y; s[2]=v0.z; s[3]=v0.w;
        #pragma unroll
        for (int q = 0; q < 4; ++q) { anb[q] = s[q] + rmnb[q]; axb[q] = s[q] + rmxb[q]; }
    }

    const float4* Trow4 = (const float4*)Tt;          // index: i*32 + lane

    // ---- Chunked forward loop: producers stage chunk ci+1 while warp 0 eats ci ----
    const int nchunks = (L + CHUNK - 2) / CHUNK;      // ceil((L-1)/CHUNK)
    for (int ci = 0; ci < nchunks; ++ci) {
        const int base = 1 + ci * CHUNK;

        if (warp != 0) {
            int ptid = tid - 32;
            float4* dst = ring4 + ((ci + 1) & 1) * (CHUNK * 32);
            int nb = base + CHUNK;
            #pragma unroll 2
            for (int i = ptid; i < CHUNK * 32; i += 96) {
                int r = nb + (i >> 5); r = r < T_ ? r : T_ - 1;
                dst[i] = lg4[r * 32 + (i & 31)];
            }
        } else {
            const float4* src = ring4 + (ci & 1) * (CHUNK * 32);
            int tend = base + CHUNK < L ? base + CHUNK : L;
            for (int t = base; t < tend; ++t) {
                float4 clt = src[(t - base) * 32 + lane];   // logit row t (smem)

                // ---- LB: REDUX.MAX on raw bits of positive floats ----
                float am  = fmaxf(fmaxf(anb[0], anb[1]), fmaxf(anb[2], anb[3]));
                int   rI  = __reduce_max_sync(F, __float_as_int(am));
                float LBfs = __int_as_float(rI);

                // per-lane candidate nibble (4 float compares, ALU-side)
                unsigned nib = (axb[0] >= LBfs ? 1u : 0u) | (axb[1] >= LBfs ? 2u : 0u)
                             | (axb[2] >= LBfs ? 4u : 0u) | (axb[3] >= LBfs ? 8u : 0u);
                unsigned qf  = nib ? (unsigned)(__ffs(nib) - 1) : 0u;  // first cand slot

                // slot-encoded ballots (all independent -> pipeline)
                unsigned em = __ballot_sync(F, nib != 0u);
                unsigned lo = __ballot_sync(F, (qf & 1u) != 0u);
                unsigned hi = __ballot_sync(F, (qf & 2u) != 0u);
                unsigned mm = __ballot_sync(F, (nib & (nib - 1u)) != 0u);

                // ---- pure-ALU decode of first two candidate lanes ----
                int cl0 = __ffs(em) - 1;                       // em != 0 always
                unsigned em2 = em & (em - 1u);
                int cl1 = em2 ? (__ffs(em2) - 1) : cl0;
                int q0 = (int)(((lo >> cl0) & 1u) | (((hi >> cl0) & 1u) << 1));
                int q1 = (int)(((lo >> cl1) & 1u) | (((hi >> cl1) & 1u) << 1));
                int i0c = (cl0 << 2) | q0;
                int i1c = (cl1 << 2) | q1;

                float w0 = q0 == 0 ? s[0] : q0 == 1 ? s[1] : q0 == 2 ? s[2] : s[3];
                float w1 = q1 == 0 ? s[0] : q1 == 1 ? s[1] : q1 == 2 ? s[2] : s[3];
                float sc0 = __shfl_sync(F, w0, cl0);
                float sc1 = __shfl_sync(F, w1, cl1);

                float4 tr0 = Trow4[i0c * 32 + lane];   // both LDS.128 in flight together
                float4 tr1 = Trow4[i1c * 32 + lane];

                float bv0, bv1, bv2, bv3;  int bi0, bi1, bi2, bi3;
                cmerge(sc0 + tr0.x, i0c, sc1 + tr1.x, i1c, bv0, bi0);
                cmerge(sc0 + tr0.y, i0c, sc1 + tr1.y, i1c, bv1, bi1);
                cmerge(sc0 + tr0.z, i0c, sc1 + tr1.z, i1c, bv2, bi2);
                cmerge(sc0 + tr0.w, i0c, sc1 + tr1.w, i1c, bv3, bi3);

                // ---- rare overflow: >=3 candidate lanes or any multi-slot lane ----
                unsigned rem = (em2 & (em2 - 1u)) | mm;
                if (rem) {
                    do {
                        int cl = __ffs(rem) - 1; rem &= rem - 1u;
                        unsigned nb = __shfl_sync(F, nib, cl);
                        while (nb) {
                            int q = __ffs(nb) - 1; nb &= nb - 1u;  // q warp-uniform
                            int i = (cl << 2) | q;
                            float sv = q == 0 ? s[0] : q == 1 ? s[1] : q == 2 ? s[2] : s[3];
                            float sc = __shfl_sync(F, sv, cl);
                            float4 tr = Trow4[i * 32 + lane];
                            cmerge(bv0, bi0, sc + tr.x, i, bv0, bi0);
                            cmerge(bv1, bi1, sc + tr.y, i, bv1, bi1);
                            cmerge(bv2, bi2, sc + tr.z, i, bv2, bi2);
                            cmerge(bv3, bi3, sc + tr.w, i, bv3, bi3);
                        }
                    } while (rem);
                }

                // ---- state update + next-step bound operands (latency shadow) ----
                s[0] = bv0 + clt.x;
                s[1] = bv1 + clt.y;
                s[2] = bv2 + clt.z;
                s[3] = bv3 + clt.w;
                anb[0] = s[0] + rmnb[0]; axb[0] = s[0] + rmxb[0];
                anb[1] = s[1] + rmnb[1]; axb[1] = s[1] + rmxb[1];
                anb[2] = s[2] + rmnb[2]; axb[2] = s[2] + rmxb[2];
                anb[3] = s[3] + rmnb[3]; axb[3] = s[3] + rmxb[3];

                bpS[t * 32 + lane] = (unsigned)bi0 | ((unsigned)bi1 << 8) |
                                     ((unsigned)bi2 << 16) | ((unsigned)bi3 << 24);
            }
        }
        __syncthreads();   // chunk handoff
    }

    if (warp == 0) {
        // ---- last_tag = first argmax of final state (exact keys, off hot path) ----
        float fm = fmaxf(fmaxf(s[0], s[1]), fmaxf(s[2], s[3]));
        int   mk = __reduce_max_sync(F, f2key(fm));
        unsigned cand = 0x7fffffffu;
        #pragma unroll
        for (int q = 0; q < 4; ++q) {
            unsigned tg = (unsigned)(4 * lane + q);
            cand = (f2key(s[q]) == mk && tg < cand) ? tg : cand;
        }
        int last = (int)__reduce_min_sync(F, cand);

        for (int t = L - 1 + lane; t < T_; t += 32) tagsS[t] = last;

        // ---- backtrack: byte-addressed LDS chain ----
        if (lane == 0) {
            const unsigned char* bpB = (const unsigned char*)bpS;
            int cur = last;
            for (int t = L - 1; t >= 1; --t) {
                cur = bpB[t * 128 + cur];
                tagsS[t - 1] = cur;
            }
        }
    }
    __syncthreads();

    // ---- one-hot epilogue: 512 KB per CTA, coalesced STG.128 ----
    float4* out4 = (float4*)(out + (size_t)b * T_ * K_);
    for (int idx = tid; idx < T_ * (K_ / 4); idx += 128) {
        int t = idx >> 5;
        int c = (idx & 31) * 4;
        int tag = tagsS[t];
        float4 v;
        v.x = (tag == c    ) ? 1.f : 0.f;
        v.y = (tag == c + 1) ? 1.f : 0.f;
        v.z = (tag == c + 2) ? 1.f : 0.f;
        v.w = (tag == c + 3) ? 1.f : 0.f;
        out4[idx] = v;
    }
}

extern "C" void kernel_launch(void* const* d_in, const int* in_sizes, int n_in,
                              void* d_out, int out_size)
{
    const float* logits = (const float*)d_in[0];
    const int*   lens   = (const int*)d_in[1];
    const float* trans  = (const float*)d_in[2];
    float*       out    = (float*)d_out;

    cudaFuncSetAttribute(viterbi_kernel,
                         cudaFuncAttributeMaxDynamicSharedMemorySize,
                         (int)SMEM_BYTES);
    viterbi_kernel<<<B_, 128, SMEM_BYTES>>>(logits, lens, trans, out);
}